// round 5
// baseline (speedup 1.0000x reference)
#include <cuda_runtime.h>

// out[i] = -(x0*x0 - x0 + x1*x1 - x1) = x0*(1-x0) + x1*(1-x1), A = 1.0
// N = 16777216 rows; input [N,2] fp32 (128 MiB), output [N,1] fp32 (64 MiB).
// Pure HBM stream, zero reuse -> streaming (evict-first) load/store hints
// and 4 independent float4 loads per thread for MLP.
//
// 8 rows per thread: 4x float4 loads, 2x float4 stores. N % 8 == 0, no tail.

__global__ void __launch_bounds__(256) poi2d_kernel(const float4* __restrict__ in,
                                                    float4* __restrict__ out,
                                                    int n_oct) {
    int i = blockIdx.x * blockDim.x + threadIdx.x;
    if (i < n_oct) {
        // 4 independent streaming loads, front-batched for MLP.
        float4 a = __ldcs(&in[4 * i + 0]);
        float4 b = __ldcs(&in[4 * i + 1]);
        float4 c = __ldcs(&in[4 * i + 2]);
        float4 d = __ldcs(&in[4 * i + 3]);

        float4 r0, r1;
        r0.x = fmaf(a.x, 1.0f - a.x, a.y * (1.0f - a.y));
        r0.y = fmaf(a.z, 1.0f - a.z, a.w * (1.0f - a.w));
        r0.z = fmaf(b.x, 1.0f - b.x, b.y * (1.0f - b.y));
        r0.w = fmaf(b.z, 1.0f - b.z, b.w * (1.0f - b.w));
        r1.x = fmaf(c.x, 1.0f - c.x, c.y * (1.0f - c.y));
        r1.y = fmaf(c.z, 1.0f - c.z, c.w * (1.0f - c.w));
        r1.z = fmaf(d.x, 1.0f - d.x, d.y * (1.0f - d.y));
        r1.w = fmaf(d.z, 1.0f - d.z, d.w * (1.0f - d.w));

        __stcs(&out[2 * i + 0], r0);
        __stcs(&out[2 * i + 1], r1);
    }
}

extern "C" void kernel_launch(void* const* d_in, const int* in_sizes, int n_in,
                              void* d_out, int out_size) {
    const float* in = (const float*)d_in[0];
    float* out = (float*)d_out;
    int n_rows = out_size;        // 16777216
    int n_oct = n_rows / 8;       // 8 rows per thread

    int threads = 256;
    int blocks = (n_oct + threads - 1) / threads;  // 8192
    poi2d_kernel<<<blocks, threads>>>((const float4*)in, (float4*)out, n_oct);
}

// round 9
// speedup vs baseline: 1.0331x; 1.0331x over previous
#include <cuda_runtime.h>

// out[i] = -(x0*x0 - x0 + x1*x1 - x1) = x0*(1-x0) + x1*(1-x1), A = 1.0
// N = 16777216 rows; input [N,2] fp32, output [N,1] fp32. HBM-streaming bound.
//
// R2 shape (known best: 27.0us kernel, DRAM 78.3%): plain cached float4 loads,
// 2 per thread (4 rows), one float4 store — with ONE change: the store uses
// __stcs (evict-first). Single-variable test vs R2; R5 confounded hints with
// deeper unroll and regressed via L1tex pressure from the extra loads.

__global__ void __launch_bounds__(256) poi2d_kernel(const float4* __restrict__ in,
                                                    float4* __restrict__ out,
                                                    int n_quads) {
    int i = blockIdx.x * blockDim.x + threadIdx.x;
    if (i < n_quads) {
        float4 a = in[2 * i];
        float4 b = in[2 * i + 1];
        float4 r;
        r.x = fmaf(a.x, 1.0f - a.x, a.y * (1.0f - a.y));
        r.y = fmaf(a.z, 1.0f - a.z, a.w * (1.0f - a.w));
        r.z = fmaf(b.x, 1.0f - b.x, b.y * (1.0f - b.y));
        r.w = fmaf(b.z, 1.0f - b.z, b.w * (1.0f - b.w));
        __stcs(&out[i], r);
    }
}

extern "C" void kernel_launch(void* const* d_in, const int* in_sizes, int n_in,
                              void* d_out, int out_size) {
    const float* in = (const float*)d_in[0];
    float* out = (float*)d_out;
    int n_rows = out_size;        // 16777216
    int n_quads = n_rows / 4;     // 4 rows (one float4 of outputs) per thread

    int threads = 256;
    int blocks = (n_quads + threads - 1) / threads;  // 16384
    poi2d_kernel<<<blocks, threads>>>((const float4*)in, (float4*)out, n_quads);
}